// round 1
// baseline (speedup 1.0000x reference)
#include <cuda_runtime.h>

// Problem constants
#define SEQ     2048
#define BATCH   2
#define HIDDEN  2048
#define NHEADS  16
#define HDIM    128
#define M_ROWS  (SEQ * BATCH)       // 4096 rows, row index = s*BATCH + b
#define QKV_N   (3 * HIDDEN)        // 6144
#define MASK_VALUE (-10000.0f)

// Scratch (device globals: allocation-free per harness rules)
__device__ float g_qkv[(size_t)M_ROWS * QKV_N];   // [4096, 6144]  q|k|v interleaved per head (384/head)
__device__ float g_ctx[(size_t)M_ROWS * HIDDEN];  // [4096, 2048]

// ---------------------------------------------------------------------------
// SGEMM: C[M,N] = A[M,K] @ B[K,N] (+ bias per column, optional)
// 128x128 block tile, BK=8, 8x8 per thread, 256 threads.
// Requires M%128==0, N%128==0, K%8==0 (true for all our shapes).
// ---------------------------------------------------------------------------
__global__ __launch_bounds__(256) void sgemm_kernel(
    const float* __restrict__ A, const float* __restrict__ B,
    const float* __restrict__ bias, float* __restrict__ C,
    int M, int N, int K)
{
    __shared__ float As[8][128];   // [k][m] (transposed on store)
    __shared__ float Bs[8][128];   // [k][n]

    const int tid  = threadIdx.x;
    const int tx   = tid & 15;     // 16 col groups of 8
    const int ty   = tid >> 4;     // 16 row groups of 8
    const int row0 = blockIdx.y * 128;
    const int col0 = blockIdx.x * 128;

    // A tile load mapping: 128 rows x 8 cols = 256 float4
    const int a_row = tid >> 1;            // 0..127
    const int a_col = (tid & 1) << 2;      // 0 or 4
    // B tile load mapping: 8 rows x 128 cols = 256 float4
    const int b_row = tid >> 5;            // 0..7
    const int b_col = (tid & 31) << 2;     // 0..124

    const float* Aptr = A + (size_t)(row0 + a_row) * K + a_col;
    const float* Bptr = B + (size_t)b_row * N + col0 + b_col;

    float acc[8][8];
    #pragma unroll
    for (int i = 0; i < 8; i++)
        #pragma unroll
        for (int j = 0; j < 8; j++) acc[i][j] = 0.0f;

    for (int k0 = 0; k0 < K; k0 += 8) {
        float4 av = *(const float4*)(Aptr + k0);
        As[a_col + 0][a_row] = av.x;
        As[a_col + 1][a_row] = av.y;
        As[a_col + 2][a_row] = av.z;
        As[a_col + 3][a_row] = av.w;
        float4 bv = *(const float4*)(Bptr + (size_t)k0 * N);
        *(float4*)&Bs[b_row][b_col] = bv;
        __syncthreads();

        #pragma unroll
        for (int k = 0; k < 8; k++) {
            float ar[8], br[8];
            *(float4*)(ar)     = *(const float4*)&As[k][ty * 8];
            *(float4*)(ar + 4) = *(const float4*)&As[k][ty * 8 + 4];
            *(float4*)(br)     = *(const float4*)&Bs[k][tx * 8];
            *(float4*)(br + 4) = *(const float4*)&Bs[k][tx * 8 + 4];
            #pragma unroll
            for (int i = 0; i < 8; i++)
                #pragma unroll
                for (int j = 0; j < 8; j++)
                    acc[i][j] = fmaf(ar[i], br[j], acc[i][j]);
        }
        __syncthreads();
    }

    #pragma unroll
    for (int i = 0; i < 8; i++) {
        const int r = row0 + ty * 8 + i;
        float* Crow = C + (size_t)r * N + col0 + tx * 8;
        #pragma unroll
        for (int j4 = 0; j4 < 8; j4 += 4) {
            float4 o;
            o.x = acc[i][j4 + 0];
            o.y = acc[i][j4 + 1];
            o.z = acc[i][j4 + 2];
            o.w = acc[i][j4 + 3];
            if (bias) {
                const float* bp = bias + col0 + tx * 8 + j4;
                o.x += bp[0]; o.y += bp[1]; o.z += bp[2]; o.w += bp[3];
            }
            *(float4*)(Crow + j4) = o;
        }
    }
}

// ---------------------------------------------------------------------------
// Flash attention (fp32, causal). One CTA = 64 query rows of one (batch, head).
// 256 threads. Score mapping: thread (ty,tx) owns 4q x 4t; PV mapping: 4q x 8d.
// smem: Qt[128][64] (d-major), Kt[128][64] (d-major), Vs[64][128] (t-major),
//       Pt[64][72] (q-major, padded), row stats.
// ---------------------------------------------------------------------------
#define BQ 64
#define BKK 64
#define PT_LD 72
#define ATTN_SMEM ((128 * 64 + 128 * 64 + 64 * 128 + 64 * PT_LD + 3 * 64) * 4)

__global__ __launch_bounds__(256) void attn_kernel(
    const float* __restrict__ qkv, float* __restrict__ ctx)
{
    extern __shared__ float sm[];
    float* Qt        = sm;                  // [128][64]
    float* Kt        = Qt + 128 * 64;       // [128][64]
    float* Vs        = Kt + 128 * 64;       // [64][128]
    float* Pt        = Vs + 64 * 128;       // [64][PT_LD]
    float* row_m     = Pt + 64 * PT_LD;     // [64]
    float* row_l     = row_m + 64;          // [64]
    float* row_scale = row_l + 64;          // [64]

    const int tid = threadIdx.x;
    const int tx  = tid & 15;
    const int ty  = tid >> 4;
    const int q0  = blockIdx.x * BQ;
    const int bh  = blockIdx.y;
    const int b   = bh >> 4;                 // batch
    const int h   = bh & 15;                 // head
    const float inv_norm = 0.08838834764831845f;   // 1/sqrt(128)

    const int head_off = h * (3 * HDIM);     // q at +0, k at +128, v at +256

    // Load Q tile transposed (d-major)
    {
        const int r = tid >> 2;
        #pragma unroll
        for (int j = 0; j < 8; j++) {
            const int d = ((tid & 3) + j * 4) * 4;
            const float* gp = qkv + (size_t)((q0 + r) * BATCH + b) * QKV_N + head_off + d;
            float4 v = *(const float4*)gp;
            Qt[(d + 0) * 64 + r] = v.x;
            Qt[(d + 1) * 64 + r] = v.y;
            Qt[(d + 2) * 64 + r] = v.z;
            Qt[(d + 3) * 64 + r] = v.w;
        }
    }
    if (tid < 64) { row_m[tid] = -1e30f; row_l[tid] = 0.0f; }

    float cacc[4][8];
    #pragma unroll
    for (int i = 0; i < 4; i++)
        #pragma unroll
        for (int j = 0; j < 8; j++) cacc[i][j] = 0.0f;

    const int ntiles = blockIdx.x + 1;       // causal: only tiles with t0 <= q0
    for (int kt = 0; kt < ntiles; kt++) {
        const int t0 = kt * BKK;

        // Load K (transposed) and V (row-major)
        {
            const int r = tid >> 2;
            #pragma unroll
            for (int j = 0; j < 8; j++) {
                const int d = ((tid & 3) + j * 4) * 4;
                const float* base = qkv + (size_t)((t0 + r) * BATCH + b) * QKV_N + head_off;
                float4 kv = *(const float4*)(base + HDIM + d);
                Kt[(d + 0) * 64 + r] = kv.x;
                Kt[(d + 1) * 64 + r] = kv.y;
                Kt[(d + 2) * 64 + r] = kv.z;
                Kt[(d + 3) * 64 + r] = kv.w;
                *(float4*)&Vs[r * 128 + d] = *(const float4*)(base + 2 * HDIM + d);
            }
        }
        __syncthreads();

        // Scores: 4x4 per thread over d=0..127
        float s[4][4];
        #pragma unroll
        for (int i = 0; i < 4; i++)
            #pragma unroll
            for (int j = 0; j < 4; j++) s[i][j] = 0.0f;

        #pragma unroll 8
        for (int d = 0; d < 128; d++) {
            float4 qv = *(const float4*)&Qt[d * 64 + ty * 4];
            float4 kv = *(const float4*)&Kt[d * 64 + tx * 4];
            float qa[4] = {qv.x, qv.y, qv.z, qv.w};
            float ka[4] = {kv.x, kv.y, kv.z, kv.w};
            #pragma unroll
            for (int i = 0; i < 4; i++)
                #pragma unroll
                for (int j = 0; j < 4; j++)
                    s[i][j] = fmaf(qa[i], ka[j], s[i][j]);
        }

        const bool diag = (kt == blockIdx.x);
        #pragma unroll
        for (int i = 0; i < 4; i++)
            #pragma unroll
            for (int j = 0; j < 4; j++) {
                float v = s[i][j] * inv_norm;
                if (diag && (tx * 4 + j > ty * 4 + i)) v = MASK_VALUE;
                s[i][j] = v;
            }

        // Online softmax per query row (16-lane reduce via shfl_xor <= 8)
        #pragma unroll
        for (int i = 0; i < 4; i++) {
            float tm = fmaxf(fmaxf(s[i][0], s[i][1]), fmaxf(s[i][2], s[i][3]));
            #pragma unroll
            for (int off = 8; off; off >>= 1)
                tm = fmaxf(tm, __shfl_xor_sync(0xffffffffu, tm, off));
            const int q = ty * 4 + i;
            const float mo = row_m[q];
            const float mn = fmaxf(mo, tm);
            float p0 = __expf(s[i][0] - mn);
            float p1 = __expf(s[i][1] - mn);
            float p2 = __expf(s[i][2] - mn);
            float p3 = __expf(s[i][3] - mn);
            float lsum = (p0 + p1) + (p2 + p3);
            #pragma unroll
            for (int off = 8; off; off >>= 1)
                lsum += __shfl_xor_sync(0xffffffffu, lsum, off);
            if (tx == 0) {
                const float sc = __expf(mo - mn);
                row_scale[q] = sc;
                row_l[q] = row_l[q] * sc + lsum;
                row_m[q] = mn;
            }
            *(float4*)&Pt[q * PT_LD + tx * 4] = make_float4(p0, p1, p2, p3);
        }
        __syncthreads();

        // PV: rescale running context, then accumulate over this key tile
        #pragma unroll
        for (int i = 0; i < 4; i++) {
            const float sc = row_scale[ty * 4 + i];
            #pragma unroll
            for (int j = 0; j < 8; j++) cacc[i][j] *= sc;
        }
        #pragma unroll 4
        for (int t = 0; t < BKK; t++) {
            const float p0 = Pt[(ty * 4 + 0) * PT_LD + t];
            const float p1 = Pt[(ty * 4 + 1) * PT_LD + t];
            const float p2 = Pt[(ty * 4 + 2) * PT_LD + t];
            const float p3 = Pt[(ty * 4 + 3) * PT_LD + t];
            float4 v0 = *(const float4*)&Vs[t * 128 + tx * 8];
            float4 v1 = *(const float4*)&Vs[t * 128 + tx * 8 + 4];
            float vv[8] = {v0.x, v0.y, v0.z, v0.w, v1.x, v1.y, v1.z, v1.w};
            #pragma unroll
            for (int j = 0; j < 8; j++) {
                cacc[0][j] = fmaf(p0, vv[j], cacc[0][j]);
                cacc[1][j] = fmaf(p1, vv[j], cacc[1][j]);
                cacc[2][j] = fmaf(p2, vv[j], cacc[2][j]);
                cacc[3][j] = fmaf(p3, vv[j], cacc[3][j]);
            }
        }
        __syncthreads();
    }

    // Normalize and write context: ctx[(s*B + b)*HIDDEN + h*128 + d]
    #pragma unroll
    for (int i = 0; i < 4; i++) {
        const int q = ty * 4 + i;
        const float inv_l = 1.0f / row_l[q];
        float* op = ctx + (size_t)((q0 + q) * BATCH + b) * HIDDEN + h * HDIM + tx * 8;
        float4 o0, o1;
        o0.x = cacc[i][0] * inv_l; o0.y = cacc[i][1] * inv_l;
        o0.z = cacc[i][2] * inv_l; o0.w = cacc[i][3] * inv_l;
        o1.x = cacc[i][4] * inv_l; o1.y = cacc[i][5] * inv_l;
        o1.z = cacc[i][6] * inv_l; o1.w = cacc[i][7] * inv_l;
        *(float4*)op       = o0;
        *(float4*)(op + 4) = o1;
    }
}

// Copy b_dense (skip_bias_add: returned separately) to output tail
__global__ void copy_bias_kernel(const float* __restrict__ b, float* __restrict__ o)
{
    const int i = blockIdx.x * blockDim.x + threadIdx.x;
    if (i < HIDDEN) o[i] = b[i];
}

// ---------------------------------------------------------------------------
// Launch
// Inputs (metadata order): hidden_states f32[2048,2,2048], attention_mask (bool,
// unused — static causal), w_qkv f32[2048,6144], b_qkv f32[6144],
// w_dense f32[2048,2048], b_dense f32[2048].
// Output: context@w_dense flattened [2048,2,2048], optionally followed by b_dense.
// ---------------------------------------------------------------------------
extern "C" void kernel_launch(void* const* d_in, const int* in_sizes, int n_in,
                              void* d_out, int out_size)
{
    const float* hidden  = (const float*)d_in[0];
    const float* w_qkv   = (const float*)d_in[2];
    const float* b_qkv   = (const float*)d_in[3];
    const float* w_dense = (const float*)d_in[4];
    const float* b_dense = (const float*)d_in[5];
    float* out = (float*)d_out;

    float* qkv = nullptr;
    float* ctx = nullptr;
    cudaGetSymbolAddress((void**)&qkv, g_qkv);
    cudaGetSymbolAddress((void**)&ctx, g_ctx);

    // 1. QKV projection: [4096,2048] @ [2048,6144] + b_qkv
    sgemm_kernel<<<dim3(QKV_N / 128, M_ROWS / 128), 256>>>(
        hidden, w_qkv, b_qkv, qkv, M_ROWS, QKV_N, HIDDEN);

    // 2. Causal flash attention per (batch, head)
    cudaFuncSetAttribute(attn_kernel,
                         cudaFuncAttributeMaxDynamicSharedMemorySize, ATTN_SMEM);
    attn_kernel<<<dim3(SEQ / BQ, BATCH * NHEADS), 256, ATTN_SMEM>>>(qkv, ctx);

    // 3. Dense projection (no bias; RowParallelLinear skip_bias_add)
    sgemm_kernel<<<dim3(HIDDEN / 128, M_ROWS / 128), 256>>>(
        ctx, w_dense, nullptr, out, M_ROWS, HIDDEN, HIDDEN);

    // 4. b_dense returned separately -> output tail (if present in out buffer)
    if (out_size >= M_ROWS * HIDDEN + HIDDEN) {
        copy_bias_kernel<<<(HIDDEN + 255) / 256, 256>>>(
            b_dense, out + (size_t)M_ROWS * HIDDEN);
    }
}

// round 5
// speedup vs baseline: 1.7239x; 1.7239x over previous
#include <cuda_runtime.h>
#include <cuda_bf16.h>
#include <cstdint>

// Problem constants
#define SEQ     2048
#define BATCH   2
#define HIDDEN  2048
#define NHEADS  16
#define HDIM    128
#define M_ROWS  (SEQ * BATCH)       // 4096
#define QKV_N   (3 * HIDDEN)        // 6144
#define MASK_VALUE (-10000.0f)

// ---------------------------------------------------------------------------
// Scratch (device globals: allocation-free per harness rules)
// ---------------------------------------------------------------------------
__device__ float g_qkv[(size_t)M_ROWS * QKV_N];
__device__ float g_ctx[(size_t)M_ROWS * HIDDEN];
__device__ __nv_bfloat16 g_Ahi[(size_t)M_ROWS * HIDDEN];
__device__ __nv_bfloat16 g_Alo[(size_t)M_ROWS * HIDDEN];
__device__ __nv_bfloat16 g_Bqkv_hi[(size_t)QKV_N * HIDDEN];  // w_qkv^T [6144,2048]
__device__ __nv_bfloat16 g_Bqkv_lo[(size_t)QKV_N * HIDDEN];
__device__ __nv_bfloat16 g_Bd_hi[(size_t)HIDDEN * HIDDEN];   // w_dense^T
__device__ __nv_bfloat16 g_Bd_lo[(size_t)HIDDEN * HIDDEN];

// ---------------------------------------------------------------------------
// Helpers
// ---------------------------------------------------------------------------
__device__ __forceinline__ uint32_t smem_to_u32(const void* p) {
    uint32_t a;
    asm("{ .reg .u64 t; cvta.to.shared.u64 t, %1; cvt.u32.u64 %0, t; }" : "=r"(a) : "l"(p));
    return a;
}
__device__ __forceinline__ void cp16(uint32_t s, const void* g) {
    asm volatile("cp.async.cg.shared.global [%0], [%1], 16;" :: "r"(s), "l"(g));
}
#define CP_COMMIT() asm volatile("cp.async.commit_group;" ::: "memory")
#define CP_WAIT(n)  asm volatile("cp.async.wait_group %0;" :: "n"(n) : "memory")

// mma.sync bf16 (baseline PTX, sm_80+; runs on tensor pipe as HMMA on sm_103)
#define MMA16816(d, a, b) \
    asm volatile("mma.sync.aligned.m16n8k16.row.col.f32.bf16.bf16.f32 " \
        "{%0,%1,%2,%3}, {%4,%5,%6,%7}, {%8,%9}, {%0,%1,%2,%3};" \
        : "+f"((d)[0]), "+f"((d)[1]), "+f"((d)[2]), "+f"((d)[3]) \
        : "r"((a)[0]), "r"((a)[1]), "r"((a)[2]), "r"((a)[3]), \
          "r"((b)[0]), "r"((b)[1]))

// ---------------------------------------------------------------------------
// Conversion kernels (bf16 hi/lo split)
// ---------------------------------------------------------------------------
__global__ void split_rm_kernel(const float* __restrict__ in,
                                __nv_bfloat16* __restrict__ hi,
                                __nv_bfloat16* __restrict__ lo, int n4)
{
    int i = blockIdx.x * blockDim.x + threadIdx.x;
    if (i >= n4) return;
    float4 v = ((const float4*)in)[i];
    __nv_bfloat16 h0 = __float2bfloat16(v.x);
    __nv_bfloat16 h1 = __float2bfloat16(v.y);
    __nv_bfloat16 h2 = __float2bfloat16(v.z);
    __nv_bfloat16 h3 = __float2bfloat16(v.w);
    __nv_bfloat16 l0 = __float2bfloat16(v.x - __bfloat162float(h0));
    __nv_bfloat16 l1 = __float2bfloat16(v.y - __bfloat162float(h1));
    __nv_bfloat16 l2 = __float2bfloat16(v.z - __bfloat162float(h2));
    __nv_bfloat16 l3 = __float2bfloat16(v.w - __bfloat162float(h3));
    ((__nv_bfloat162*)hi)[2 * i]     = __nv_bfloat162(h0, h1);
    ((__nv_bfloat162*)hi)[2 * i + 1] = __nv_bfloat162(h2, h3);
    ((__nv_bfloat162*)lo)[2 * i]     = __nv_bfloat162(l0, l1);
    ((__nv_bfloat162*)lo)[2 * i + 1] = __nv_bfloat162(l2, l3);
}

// in fp32 [K,N] -> hi/lo bf16 [N,K]
__global__ void split_tr_kernel(const float* __restrict__ in,
                                __nv_bfloat16* __restrict__ hi,
                                __nv_bfloat16* __restrict__ lo, int K, int N)
{
    __shared__ float t[32][33];
    const int n0 = blockIdx.x * 32, k0 = blockIdx.y * 32;
    const int tx = threadIdx.x, ty = threadIdx.y;   // 32 x 8
    #pragma unroll
    for (int i = 0; i < 4; i++)
        t[ty + 8 * i][tx] = in[(size_t)(k0 + ty + 8 * i) * N + n0 + tx];
    __syncthreads();
    #pragma unroll
    for (int i = 0; i < 4; i++) {
        const int r = ty + 8 * i;
        const float x = t[tx][r];
        __nv_bfloat16 h = __float2bfloat16(x);
        __nv_bfloat16 l = __float2bfloat16(x - __bfloat162float(h));
        const size_t o = (size_t)(n0 + r) * K + k0 + tx;
        hi[o] = h; lo[o] = l;
    }
}

// ---------------------------------------------------------------------------
// bf16x3 mma.sync GEMM: C[M,N] = A[M,K] @ B^T  (B stored [N,K] K-major)
// D = AhBh + AhBl + AlBh, fp32 accumulators in registers.
// CTA 128x128, BK=32, 8 warps (warp tile 32x64), cp.async double buffer.
// smem row stride 40 bf16 (pad) -> conflict-free fragment lds.b32.
// ---------------------------------------------------------------------------
#define GBK 32
#define LDS_STRIDE 40                               // bf16 elements per row
#define MAT_BYTES (128 * LDS_STRIDE * 2)            // 10240
#define STAGE_BYTES (4 * MAT_BYTES)                 // 40960 (Ahi,Alo,Bhi,Blo)
#define GEMM_SMEM (2 * STAGE_BYTES)                 // 81920

__global__ __launch_bounds__(256) void gemm_bf16x3_mma_kernel(
    const __nv_bfloat16* __restrict__ Ahi, const __nv_bfloat16* __restrict__ Alo,
    const __nv_bfloat16* __restrict__ Bhi, const __nv_bfloat16* __restrict__ Blo,
    const float* __restrict__ bias, float* __restrict__ C,
    int M, int N, int K)
{
    extern __shared__ char smem[];
    const uint32_t sbase = smem_to_u32(smem);
    const int tid  = threadIdx.x;
    const int wid  = tid >> 5;
    const int lane = tid & 31;
    const int g    = lane >> 2;          // 0..7
    const int tq   = lane & 3;           // 0..3
    const int wm   = wid & 3;            // warp m index (4)
    const int wn   = wid >> 2;           // warp n index (2)
    const int row0 = blockIdx.y * 128;
    const int col0 = blockIdx.x * 128;
    const int NC   = K / GBK;

    // per-thread load mapping: 2 uint4 per matrix per stage
    const int l_row  = tid >> 2;              // idx/4 for i=0 -> rows 0..63; i=1 -> 64..127
    const int l_kc   = (tid & 3) * 8;         // k element offset (0,8,16,24)

    float acc[2][8][4];
    #pragma unroll
    for (int mt = 0; mt < 2; mt++)
        #pragma unroll
        for (int nt = 0; nt < 8; nt++)
            #pragma unroll
            for (int q = 0; q < 4; q++) acc[mt][nt][q] = 0.0f;

    // ---- async load of one stage ----
    auto load_stage = [&](int st, int kc) {
        const int kel = kc * GBK;
        const uint32_t stb = sbase + (uint32_t)st * STAGE_BYTES;
        #pragma unroll
        for (int i = 0; i < 2; i++) {
            const int row = l_row + i * 64;
            const uint32_t soff = (uint32_t)(row * LDS_STRIDE + l_kc) * 2;
            const size_t ga = (size_t)(row0 + row) * K + kel + l_kc;
            const size_t gb = (size_t)(col0 + row) * K + kel + l_kc;
            cp16(stb + 0 * MAT_BYTES + soff, Ahi + ga);
            cp16(stb + 1 * MAT_BYTES + soff, Alo + ga);
            cp16(stb + 2 * MAT_BYTES + soff, Bhi + gb);
            cp16(stb + 3 * MAT_BYTES + soff, Blo + gb);
        }
        CP_COMMIT();
    };

    load_stage(0, 0);

    for (int kc = 0; kc < NC; kc++) {
        const int st = kc & 1;
        if (kc + 1 < NC) {
            load_stage(st ^ 1, kc + 1);
            CP_WAIT(1);
        } else {
            CP_WAIT(0);
        }
        __syncthreads();

        const __nv_bfloat16* sAh = (const __nv_bfloat16*)(smem + st * STAGE_BYTES);
        const __nv_bfloat16* sAl = sAh + 128 * LDS_STRIDE;
        const __nv_bfloat16* sBh = sAl + 128 * LDS_STRIDE;
        const __nv_bfloat16* sBl = sBh + 128 * LDS_STRIDE;

        #pragma unroll
        for (int ks = 0; ks < GBK; ks += 16) {
            // A fragments: 2 m-tiles x (hi,lo) x 4 regs
            uint32_t ah[2][4], al[2][4];
            #pragma unroll
            for (int mt = 0; mt < 2; mt++) {
                const int r = wm * 32 + mt * 16 + g;
                const int c = ks + tq * 2;
                ah[mt][0] = *(const uint32_t*)&sAh[(r)     * LDS_STRIDE + c];
                ah[mt][1] = *(const uint32_t*)&sAh[(r + 8) * LDS_STRIDE + c];
                ah[mt][2] = *(const uint32_t*)&sAh[(r)     * LDS_STRIDE + c + 8];
                ah[mt][3] = *(const uint32_t*)&sAh[(r + 8) * LDS_STRIDE + c + 8];
                al[mt][0] = *(const uint32_t*)&sAl[(r)     * LDS_STRIDE + c];
                al[mt][1] = *(const uint32_t*)&sAl[(r + 8) * LDS_STRIDE + c];
                al[mt][2] = *(const uint32_t*)&sAl[(r)     * LDS_STRIDE + c + 8];
                al[mt][3] = *(const uint32_t*)&sAl[(r + 8) * LDS_STRIDE + c + 8];
            }
            // B fragments: 8 n-tiles x (hi,lo) x 2 regs
            uint32_t bh[8][2], bl[8][2];
            #pragma unroll
            for (int nt = 0; nt < 8; nt++) {
                const int n = wn * 64 + nt * 8 + g;
                const int c = ks + tq * 2;
                bh[nt][0] = *(const uint32_t*)&sBh[n * LDS_STRIDE + c];
                bh[nt][1] = *(const uint32_t*)&sBh[n * LDS_STRIDE + c + 8];
                bl[nt][0] = *(const uint32_t*)&sBl[n * LDS_STRIDE + c];
                bl[nt][1] = *(const uint32_t*)&sBl[n * LDS_STRIDE + c + 8];
            }
            #pragma unroll
            for (int mt = 0; mt < 2; mt++)
                #pragma unroll
                for (int nt = 0; nt < 8; nt++) {
                    MMA16816(acc[mt][nt], ah[mt], bh[nt]);
                    MMA16816(acc[mt][nt], ah[mt], bl[nt]);
                    MMA16816(acc[mt][nt], al[mt], bh[nt]);
                }
        }
        __syncthreads();
    }

    // Epilogue: direct register -> gmem (float2 per quad), optional bias
    #pragma unroll
    for (int mt = 0; mt < 2; mt++) {
        const int r1 = row0 + wm * 32 + mt * 16 + g;
        const int r2 = r1 + 8;
        #pragma unroll
        for (int nt = 0; nt < 8; nt++) {
            const int c = col0 + wn * 64 + nt * 8 + tq * 2;
            float2 o1 = make_float2(acc[mt][nt][0], acc[mt][nt][1]);
            float2 o2 = make_float2(acc[mt][nt][2], acc[mt][nt][3]);
            if (bias) {
                const float b0 = bias[c], b1 = bias[c + 1];
                o1.x += b0; o1.y += b1;
                o2.x += b0; o2.y += b1;
            }
            *(float2*)(C + (size_t)r1 * N + c) = o1;
            *(float2*)(C + (size_t)r2 * N + c) = o2;
        }
    }
}

// ---------------------------------------------------------------------------
// Flash attention (fp32, causal) — unchanged from passing R1 kernel
// ---------------------------------------------------------------------------
#define BQ 64
#define BKK 64
#define PT_LD 72
#define ATTN_SMEM ((128 * 64 + 128 * 64 + 64 * 128 + 64 * PT_LD + 3 * 64) * 4)

__global__ __launch_bounds__(256) void attn_kernel(
    const float* __restrict__ qkv, float* __restrict__ ctx)
{
    extern __shared__ float sm[];
    float* Qt        = sm;
    float* Kt        = Qt + 128 * 64;
    float* Vs        = Kt + 128 * 64;
    float* Pt        = Vs + 64 * 128;
    float* row_m     = Pt + 64 * PT_LD;
    float* row_l     = row_m + 64;
    float* row_scale = row_l + 64;

    const int tid = threadIdx.x;
    const int tx  = tid & 15;
    const int ty  = tid >> 4;
    const int q0  = blockIdx.x * BQ;
    const int bh  = blockIdx.y;
    const int b   = bh >> 4;
    const int h   = bh & 15;
    const float inv_norm = 0.08838834764831845f;
    const int head_off = h * (3 * HDIM);

    {
        const int r = tid >> 2;
        #pragma unroll
        for (int j = 0; j < 8; j++) {
            const int d = ((tid & 3) + j * 4) * 4;
            const float* gp = qkv + (size_t)((q0 + r) * BATCH + b) * QKV_N + head_off + d;
            float4 v = *(const float4*)gp;
            Qt[(d + 0) * 64 + r] = v.x;
            Qt[(d + 1) * 64 + r] = v.y;
            Qt[(d + 2) * 64 + r] = v.z;
            Qt[(d + 3) * 64 + r] = v.w;
        }
    }
    if (tid < 64) { row_m[tid] = -1e30f; row_l[tid] = 0.0f; }

    float cacc[4][8];
    #pragma unroll
    for (int i = 0; i < 4; i++)
        #pragma unroll
        for (int j = 0; j < 8; j++) cacc[i][j] = 0.0f;

    const int ntiles = blockIdx.x + 1;
    for (int kt = 0; kt < ntiles; kt++) {
        const int t0 = kt * BKK;
        {
            const int r = tid >> 2;
            #pragma unroll
            for (int j = 0; j < 8; j++) {
                const int d = ((tid & 3) + j * 4) * 4;
                const float* base = qkv + (size_t)((t0 + r) * BATCH + b) * QKV_N + head_off;
                float4 kv = *(const float4*)(base + HDIM + d);
                Kt[(d + 0) * 64 + r] = kv.x;
                Kt[(d + 1) * 64 + r] = kv.y;
                Kt[(d + 2) * 64 + r] = kv.z;
                Kt[(d + 3) * 64 + r] = kv.w;
                *(float4*)&Vs[r * 128 + d] = *(const float4*)(base + 2 * HDIM + d);
            }
        }
        __syncthreads();

        float s[4][4];
        #pragma unroll
        for (int i = 0; i < 4; i++)
            #pragma unroll
            for (int j = 0; j < 4; j++) s[i][j] = 0.0f;

        #pragma unroll 8
        for (int d = 0; d < 128; d++) {
            float4 qv = *(const float4*)&Qt[d * 64 + ty * 4];
            float4 kv = *(const float4*)&Kt[d * 64 + tx * 4];
            float qa[4] = {qv.x, qv.y, qv.z, qv.w};
            float ka[4] = {kv.x, kv.y, kv.z, kv.w};
            #pragma unroll
            for (int i = 0; i < 4; i++)
                #pragma unroll
                for (int j = 0; j < 4; j++)
                    s[i][j] = fmaf(qa[i], ka[j], s[i][j]);
        }

        const bool diag = (kt == blockIdx.x);
        #pragma unroll
        for (int i = 0; i < 4; i++)
            #pragma unroll
            for (int j = 0; j < 4; j++) {
                float v = s[i][j] * inv_norm;
                if (diag && (tx * 4 + j > ty * 4 + i)) v = MASK_VALUE;
                s[i][j] = v;
            }

        #pragma unroll
        for (int i = 0; i < 4; i++) {
            float tm = fmaxf(fmaxf(s[i][0], s[i][1]), fmaxf(s[i][2], s[i][3]));
            #pragma unroll
            for (int off = 8; off; off >>= 1)
                tm = fmaxf(tm, __shfl_xor_sync(0xffffffffu, tm, off));
            const int q = ty * 4 + i;
            const float mo = row_m[q];
            const float mn = fmaxf(mo, tm);
            float p0 = __expf(s[i][0] - mn);
            float p1 = __expf(s[i][1] - mn);
            float p2 = __expf(s[i][2] - mn);
            float p3 = __expf(s[i][3] - mn);
            float lsum = (p0 + p1) + (p2 + p3);
            #pragma unroll
            for (int off = 8; off; off >>= 1)
                lsum += __shfl_xor_sync(0xffffffffu, lsum, off);
            if (tx == 0) {
                const float sc = __expf(mo - mn);
                row_scale[q] = sc;
                row_l[q] = row_l[q] * sc + lsum;
                row_m[q] = mn;
            }
            *(float4*)&Pt[q * PT_LD + tx * 4] = make_float4(p0, p1, p2, p3);
        }
        __syncthreads();

        #pragma unroll
        for (int i = 0; i < 4; i++) {
            const float sc = row_scale[ty * 4 + i];
            #pragma unroll
            for (int j = 0; j < 8; j++) cacc[i][j] *= sc;
        }
        #pragma unroll 4
        for (int t = 0; t < BKK; t++) {
            const float p0 = Pt[(ty * 4 + 0) * PT_LD + t];
            const float p1 = Pt[(ty * 4 + 1) * PT_LD + t];
            const float p2 = Pt[(ty * 4 + 2) * PT_LD + t];
            const float p3 = Pt[(ty * 4 + 3) * PT_LD + t];
            float4 v0 = *(const float4*)&Vs[t * 128 + tx * 8];
            float4 v1 = *(const float4*)&Vs[t * 128 + tx * 8 + 4];
            float vv[8] = {v0.x, v0.y, v0.z, v0.w, v1.x, v1.y, v1.z, v1.w};
            #pragma unroll
            for (int j = 0; j < 8; j++) {
                cacc[0][j] = fmaf(p0, vv[j], cacc[0][j]);
                cacc[1][j] = fmaf(p1, vv[j], cacc[1][j]);
                cacc[2][j] = fmaf(p2, vv[j], cacc[2][j]);
                cacc[3][j] = fmaf(p3, vv[j], cacc[3][j]);
            }
        }
        __syncthreads();
    }

    #pragma unroll
    for (int i = 0; i < 4; i++) {
        const int q = ty * 4 + i;
        const float inv_l = 1.0f / row_l[q];
        float* op = ctx + (size_t)((q0 + q) * BATCH + b) * HIDDEN + h * HDIM + tx * 8;
        float4 o0, o1;
        o0.x = cacc[i][0] * inv_l; o0.y = cacc[i][1] * inv_l;
        o0.z = cacc[i][2] * inv_l; o0.w = cacc[i][3] * inv_l;
        o1.x = cacc[i][4] * inv_l; o1.y = cacc[i][5] * inv_l;
        o1.z = cacc[i][6] * inv_l; o1.w = cacc[i][7] * inv_l;
        *(float4*)op       = o0;
        *(float4*)(op + 4) = o1;
    }
}

__global__ void copy_bias_kernel(const float* __restrict__ b, float* __restrict__ o)
{
    const int i = blockIdx.x * blockDim.x + threadIdx.x;
    if (i < HIDDEN) o[i] = b[i];
}

// ---------------------------------------------------------------------------
// Launch
// ---------------------------------------------------------------------------
extern "C" void kernel_launch(void* const* d_in, const int* in_sizes, int n_in,
                              void* d_out, int out_size)
{
    const float* hidden  = (const float*)d_in[0];
    const float* w_qkv   = (const float*)d_in[2];
    const float* b_qkv   = (const float*)d_in[3];
    const float* w_dense = (const float*)d_in[4];
    const float* b_dense = (const float*)d_in[5];
    float* out = (float*)d_out;

    float *qkv = nullptr, *ctx = nullptr;
    __nv_bfloat16 *Ahi, *Alo, *Bqh, *Bql, *Bdh, *Bdl;
    cudaGetSymbolAddress((void**)&qkv, g_qkv);
    cudaGetSymbolAddress((void**)&ctx, g_ctx);
    cudaGetSymbolAddress((void**)&Ahi, g_Ahi);
    cudaGetSymbolAddress((void**)&Alo, g_Alo);
    cudaGetSymbolAddress((void**)&Bqh, g_Bqkv_hi);
    cudaGetSymbolAddress((void**)&Bql, g_Bqkv_lo);
    cudaGetSymbolAddress((void**)&Bdh, g_Bd_hi);
    cudaGetSymbolAddress((void**)&Bdl, g_Bd_lo);

    cudaFuncSetAttribute(gemm_bf16x3_mma_kernel,
                         cudaFuncAttributeMaxDynamicSharedMemorySize, GEMM_SMEM);
    cudaFuncSetAttribute(attn_kernel,
                         cudaFuncAttributeMaxDynamicSharedMemorySize, ATTN_SMEM);

    const int n4_act = (M_ROWS * HIDDEN) / 4;

    // 1. Split inputs + weights for QKV
    split_rm_kernel<<<(n4_act + 255) / 256, 256>>>(hidden, Ahi, Alo, n4_act);
    split_tr_kernel<<<dim3(QKV_N / 32, HIDDEN / 32), dim3(32, 8)>>>(
        w_qkv, Bqh, Bql, HIDDEN, QKV_N);

    // 2. QKV projection (mma.sync bf16x3): [4096,2048]@[2048,6144] + b_qkv
    gemm_bf16x3_mma_kernel<<<dim3(QKV_N / 128, M_ROWS / 128), 256, GEMM_SMEM>>>(
        Ahi, Alo, Bqh, Bql, b_qkv, qkv, M_ROWS, QKV_N, HIDDEN);

    // 3. Causal flash attention (fp32 SIMT)
    attn_kernel<<<dim3(SEQ / BQ, BATCH * NHEADS), 256, ATTN_SMEM>>>(qkv, ctx);

    // 4. Split ctx + w_dense, dense projection (no bias: skip_bias_add)
    split_rm_kernel<<<(n4_act + 255) / 256, 256>>>(ctx, Ahi, Alo, n4_act);
    split_tr_kernel<<<dim3(HIDDEN / 32, HIDDEN / 32), dim3(32, 8)>>>(
        w_dense, Bdh, Bdl, HIDDEN, HIDDEN);
    gemm_bf16x3_mma_kernel<<<dim3(HIDDEN / 128, M_ROWS / 128), 256, GEMM_SMEM>>>(
        Ahi, Alo, Bdh, Bdl, nullptr, out, M_ROWS, HIDDEN, HIDDEN);

    // 5. b_dense returned separately -> output tail (if present)
    if (out_size >= M_ROWS * HIDDEN + HIDDEN) {
        copy_bias_kernel<<<(HIDDEN + 255) / 256, 256>>>(
            b_dense, out + (size_t)M_ROWS * HIDDEN);
    }
}

// round 7
// speedup vs baseline: 2.6922x; 1.5617x over previous
#include <cuda_runtime.h>
#include <cuda_bf16.h>
#include <cstdint>

// Problem constants
#define SEQ     2048
#define BATCH   2
#define HIDDEN  2048
#define NHEADS  16
#define HDIM    128
#define M_ROWS  (SEQ * BATCH)       // 4096
#define QKV_N   (3 * HIDDEN)        // 6144

// ---------------------------------------------------------------------------
// Scratch (device globals: allocation-free per harness rules)
// ---------------------------------------------------------------------------
__device__ float g_qkv[(size_t)M_ROWS * QKV_N];
__device__ float g_ctx[(size_t)M_ROWS * HIDDEN];
__device__ __nv_bfloat16 g_Ahi[(size_t)M_ROWS * HIDDEN];
__device__ __nv_bfloat16 g_Alo[(size_t)M_ROWS * HIDDEN];
__device__ __nv_bfloat16 g_Bqkv_hi[(size_t)QKV_N * HIDDEN];
__device__ __nv_bfloat16 g_Bqkv_lo[(size_t)QKV_N * HIDDEN];
__device__ __nv_bfloat16 g_Bd_hi[(size_t)HIDDEN * HIDDEN];
__device__ __nv_bfloat16 g_Bd_lo[(size_t)HIDDEN * HIDDEN];
// attention per-head split arrays [bh][s][d], bh = b*16+h
#define HSZ ((size_t)32 * SEQ * HDIM)
__device__ __nv_bfloat16 g_Qh[HSZ];
__device__ __nv_bfloat16 g_Ql[HSZ];
__device__ __nv_bfloat16 g_Kh[HSZ];
__device__ __nv_bfloat16 g_Kl[HSZ];
__device__ __nv_bfloat16 g_Vh[HSZ];
__device__ __nv_bfloat16 g_Vl[HSZ];

// ---------------------------------------------------------------------------
// Helpers
// ---------------------------------------------------------------------------
__device__ __forceinline__ uint32_t smem_to_u32(const void* p) {
    uint32_t a;
    asm("{ .reg .u64 t; cvta.to.shared.u64 t, %1; cvt.u32.u64 %0, t; }" : "=r"(a) : "l"(p));
    return a;
}
__device__ __forceinline__ void cp16(uint32_t s, const void* g) {
    asm volatile("cp.async.cg.shared.global [%0], [%1], 16;" :: "r"(s), "l"(g));
}
#define CP_COMMIT() asm volatile("cp.async.commit_group;" ::: "memory")
#define CP_WAIT(n)  asm volatile("cp.async.wait_group %0;" :: "n"(n) : "memory")

#define MMA16816(d, a, b) \
    asm volatile("mma.sync.aligned.m16n8k16.row.col.f32.bf16.bf16.f32 " \
        "{%0,%1,%2,%3}, {%4,%5,%6,%7}, {%8,%9}, {%0,%1,%2,%3};" \
        : "+f"((d)[0]), "+f"((d)[1]), "+f"((d)[2]), "+f"((d)[3]) \
        : "r"((a)[0]), "r"((a)[1]), "r"((a)[2]), "r"((a)[3]), \
          "r"((b)[0]), "r"((b)[1]))

#define LDSM4(r, addr) \
    asm volatile("ldmatrix.sync.aligned.m8n8.x4.shared.b16 {%0,%1,%2,%3}, [%4];" \
        : "=r"((r)[0]), "=r"((r)[1]), "=r"((r)[2]), "=r"((r)[3]) : "r"(addr))
#define LDSM4T(r, addr) \
    asm volatile("ldmatrix.sync.aligned.m8n8.x4.trans.shared.b16 {%0,%1,%2,%3}, [%4];" \
        : "=r"((r)[0]), "=r"((r)[1]), "=r"((r)[2]), "=r"((r)[3]) : "r"(addr))

__device__ __forceinline__ uint32_t bf2pack(float a, float b) {
    __nv_bfloat162 t = __floats2bfloat162_rn(a, b);
    return *(uint32_t*)&t;
}
__device__ __forceinline__ float bf16res(float x) {
    return x - __bfloat162float(__float2bfloat16(x));
}

// ---------------------------------------------------------------------------
// Conversion kernels
// ---------------------------------------------------------------------------
__global__ void split_rm_kernel(const float* __restrict__ in,
                                __nv_bfloat16* __restrict__ hi,
                                __nv_bfloat16* __restrict__ lo, int n4)
{
    int i = blockIdx.x * blockDim.x + threadIdx.x;
    if (i >= n4) return;
    float4 v = ((const float4*)in)[i];
    __nv_bfloat16 h0 = __float2bfloat16(v.x);
    __nv_bfloat16 h1 = __float2bfloat16(v.y);
    __nv_bfloat16 h2 = __float2bfloat16(v.z);
    __nv_bfloat16 h3 = __float2bfloat16(v.w);
    __nv_bfloat16 l0 = __float2bfloat16(v.x - __bfloat162float(h0));
    __nv_bfloat16 l1 = __float2bfloat16(v.y - __bfloat162float(h1));
    __nv_bfloat16 l2 = __float2bfloat16(v.z - __bfloat162float(h2));
    __nv_bfloat16 l3 = __float2bfloat16(v.w - __bfloat162float(h3));
    ((__nv_bfloat162*)hi)[2 * i]     = __nv_bfloat162(h0, h1);
    ((__nv_bfloat162*)hi)[2 * i + 1] = __nv_bfloat162(h2, h3);
    ((__nv_bfloat162*)lo)[2 * i]     = __nv_bfloat162(l0, l1);
    ((__nv_bfloat162*)lo)[2 * i + 1] = __nv_bfloat162(l2, l3);
}

__global__ void split_tr_kernel(const float* __restrict__ in,
                                __nv_bfloat16* __restrict__ hi,
                                __nv_bfloat16* __restrict__ lo, int K, int N)
{
    __shared__ float t[32][33];
    const int n0 = blockIdx.x * 32, k0 = blockIdx.y * 32;
    const int tx = threadIdx.x, ty = threadIdx.y;
    #pragma unroll
    for (int i = 0; i < 4; i++)
        t[ty + 8 * i][tx] = in[(size_t)(k0 + ty + 8 * i) * N + n0 + tx];
    __syncthreads();
    #pragma unroll
    for (int i = 0; i < 4; i++) {
        const int r = ty + 8 * i;
        const float x = t[tx][r];
        __nv_bfloat16 h = __float2bfloat16(x);
        __nv_bfloat16 l = __float2bfloat16(x - __bfloat162float(h));
        const size_t o = (size_t)(n0 + r) * K + k0 + tx;
        hi[o] = h; lo[o] = l;
    }
}

// g_qkv fp32 -> per-head bf16 hi/lo arrays. Q pre-scaled by 1/sqrt(128).
__global__ void qkv_split_kernel(const float* __restrict__ qkv)
{
    const int idx = blockIdx.x * blockDim.x + threadIdx.x;  // < 32*2048*32
    const int d4 = idx & 31;
    const int s  = (idx >> 5) & 2047;
    const int bh = idx >> 16;
    const int b = bh >> 4, h = bh & 15;
    const float* src = qkv + (size_t)(s * 2 + b) * QKV_N + h * 384 + d4 * 4;
    const size_t dst = ((size_t)bh * SEQ + s) * HDIM + d4 * 4;
    const float qs = 0.08838834764831845f;

    float4 q = *(const float4*)(src);
    float4 k = *(const float4*)(src + 128);
    float4 v = *(const float4*)(src + 256);
    q.x *= qs; q.y *= qs; q.z *= qs; q.w *= qs;

    #pragma unroll
    for (int m = 0; m < 3; m++) {
        float4 x = (m == 0) ? q : (m == 1) ? k : v;
        __nv_bfloat16* hi = (m == 0) ? g_Qh : (m == 1) ? g_Kh : g_Vh;
        __nv_bfloat16* lo = (m == 0) ? g_Ql : (m == 1) ? g_Kl : g_Vl;
        __nv_bfloat162 h01 = __nv_bfloat162(__float2bfloat16(x.x), __float2bfloat16(x.y));
        __nv_bfloat162 h23 = __nv_bfloat162(__float2bfloat16(x.z), __float2bfloat16(x.w));
        __nv_bfloat162 l01 = __nv_bfloat162(__float2bfloat16(x.x - __bfloat162float(h01.x)),
                                            __float2bfloat16(x.y - __bfloat162float(h01.y)));
        __nv_bfloat162 l23 = __nv_bfloat162(__float2bfloat16(x.z - __bfloat162float(h23.x)),
                                            __float2bfloat16(x.w - __bfloat162float(h23.y)));
        *(__nv_bfloat162*)(hi + dst)     = h01;
        *(__nv_bfloat162*)(hi + dst + 2) = h23;
        *(__nv_bfloat162*)(lo + dst)     = l01;
        *(__nv_bfloat162*)(lo + dst + 2) = l23;
    }
}

// ---------------------------------------------------------------------------
// bf16x3 mma.sync GEMM with ldmatrix fragment loads.
// C[M,N] = A[M,K] @ B^T (B stored [N,K]); D = AhBh + AhBl + AlBh.
// CTA 128x128, BK=32, 8 warps, cp.async double buffer, stride-40 smem rows.
// ---------------------------------------------------------------------------
#define GBK 32
#define LDS_STRIDE 40
#define MAT_BYTES (128 * LDS_STRIDE * 2)
#define STAGE_BYTES (4 * MAT_BYTES)
#define GEMM_SMEM (2 * STAGE_BYTES)

__global__ __launch_bounds__(256) void gemm_bf16x3_mma_kernel(
    const __nv_bfloat16* __restrict__ Ahi, const __nv_bfloat16* __restrict__ Alo,
    const __nv_bfloat16* __restrict__ Bhi, const __nv_bfloat16* __restrict__ Blo,
    const float* __restrict__ bias, float* __restrict__ C,
    int M, int N, int K)
{
    extern __shared__ char smem[];
    const uint32_t sbase = smem_to_u32(smem);
    const int tid  = threadIdx.x;
    const int wid  = tid >> 5;
    const int lane = tid & 31;
    const int g    = lane >> 2;
    const int tq   = lane & 3;
    const int wm   = wid & 3;
    const int wn   = wid >> 2;
    const int row0 = blockIdx.y * 128;
    const int col0 = blockIdx.x * 128;
    const int NC   = K / GBK;

    const int l_row = tid >> 2;
    const int l_kc  = (tid & 3) * 8;

    float acc[2][8][4];
    #pragma unroll
    for (int mt = 0; mt < 2; mt++)
        #pragma unroll
        for (int nt = 0; nt < 8; nt++)
            #pragma unroll
            for (int q = 0; q < 4; q++) acc[mt][nt][q] = 0.0f;

    auto load_stage = [&](int st, int kc) {
        const int kel = kc * GBK;
        const uint32_t stb = sbase + (uint32_t)st * STAGE_BYTES;
        #pragma unroll
        for (int i = 0; i < 2; i++) {
            const int row = l_row + i * 64;
            const uint32_t soff = (uint32_t)(row * LDS_STRIDE + l_kc) * 2;
            const size_t ga = (size_t)(row0 + row) * K + kel + l_kc;
            const size_t gb = (size_t)(col0 + row) * K + kel + l_kc;
            cp16(stb + 0 * MAT_BYTES + soff, Ahi + ga);
            cp16(stb + 1 * MAT_BYTES + soff, Alo + ga);
            cp16(stb + 2 * MAT_BYTES + soff, Bhi + gb);
            cp16(stb + 3 * MAT_BYTES + soff, Blo + gb);
        }
        CP_COMMIT();
    };

    load_stage(0, 0);

    // ldmatrix lane address components (element offsets within a matrix)
    const int a_r = wm * 32 + (lane & 15);                       // + mt*16
    const int a_c = (lane >> 4) << 3;                            // + ks
    const int b_r = wn * 64 + (lane & 7) + (((lane >> 4) & 1) << 3);  // + np*16
    const int b_c = ((lane >> 3) & 1) << 3;                      // + ks

    for (int kc = 0; kc < NC; kc++) {
        const int st = kc & 1;
        if (kc + 1 < NC) { load_stage(st ^ 1, kc + 1); CP_WAIT(1); }
        else             { CP_WAIT(0); }
        __syncthreads();

        const uint32_t stb = sbase + (uint32_t)st * STAGE_BYTES;

        #pragma unroll
        for (int ks = 0; ks < GBK; ks += 16) {
            uint32_t ah[2][4], al[2][4];
            #pragma unroll
            for (int mt = 0; mt < 2; mt++) {
                const uint32_t aa = stb + (uint32_t)(((a_r + mt * 16) * LDS_STRIDE) + ks + a_c) * 2;
                LDSM4(ah[mt], aa);
                LDSM4(al[mt], aa + MAT_BYTES);
            }
            uint32_t bh[4][4], bl[4][4];
            #pragma unroll
            for (int np = 0; np < 4; np++) {
                const uint32_t ba = stb + 2 * MAT_BYTES
                    + (uint32_t)(((b_r + np * 16) * LDS_STRIDE) + ks + b_c) * 2;
                LDSM4(bh[np], ba);
                LDSM4(bl[np], ba + MAT_BYTES);
            }
            #pragma unroll
            for (int mt = 0; mt < 2; mt++)
                #pragma unroll
                for (int nt = 0; nt < 8; nt++) {
                    uint32_t* bhp = &bh[nt >> 1][(nt & 1) * 2];
                    uint32_t* blp = &bl[nt >> 1][(nt & 1) * 2];
                    MMA16816(acc[mt][nt], ah[mt], bhp);
                    MMA16816(acc[mt][nt], ah[mt], blp);
                    MMA16816(acc[mt][nt], al[mt], bhp);
                }
        }
        __syncthreads();
    }

    #pragma unroll
    for (int mt = 0; mt < 2; mt++) {
        const int r1 = row0 + wm * 32 + mt * 16 + g;
        const int r2 = r1 + 8;
        #pragma unroll
        for (int nt = 0; nt < 8; nt++) {
            const int c = col0 + wn * 64 + nt * 8 + tq * 2;
            float2 o1 = make_float2(acc[mt][nt][0], acc[mt][nt][1]);
            float2 o2 = make_float2(acc[mt][nt][2], acc[mt][nt][3]);
            if (bias) {
                const float b0 = bias[c], b1 = bias[c + 1];
                o1.x += b0; o1.y += b1;
                o2.x += b0; o2.y += b1;
            }
            *(float2*)(C + (size_t)r1 * N + c) = o1;
            *(float2*)(C + (size_t)r2 * N + c) = o2;
        }
    }
}

// ---------------------------------------------------------------------------
// Flash attention, bf16x3 mma.sync, causal.
// CTA: 128 q rows x one (b,h); 2 passes (qtile a and 15-a for load balance).
// 8 warps, each m16. Key tiles of 64, K/V double-buffered via cp.async.
// smem: Qh/Ql [128][136], per stage Kh/Kl/Vh/Vl [64][136].
// ---------------------------------------------------------------------------
#define AST 136
#define Q_BYTES (128 * AST * 2)
#define KV_MAT (64 * AST * 2)
#define KV_STAGE (4 * KV_MAT)
#define ATTN_SMEM (2 * Q_BYTES + 2 * KV_STAGE)   // 208896

__global__ __launch_bounds__(256) void attn_mma_kernel(float* __restrict__ ctx)
{
    extern __shared__ char smem[];
    const uint32_t sb = smem_to_u32(smem);
    const int tid  = threadIdx.x;
    const int lane = tid & 31;
    const int w    = tid >> 5;
    const int g    = lane >> 2;
    const int tq   = lane & 3;
    const int bh   = blockIdx.y;
    const int b    = bh >> 4;
    const int h    = bh & 15;
    const size_t head_base = (size_t)bh * SEQ * HDIM;

    // ldmatrix address components
    const int qa_r = w * 16 + (lane & 15);
    const int qa_c = (lane >> 4) << 3;
    const int kb_r = (lane & 7) + (((lane >> 4) & 1) << 3);     // + np*16
    const int kb_c = ((lane >> 3) & 1) << 3;
    const int vt_r = lane & 15;                                  // + k2*16
    const int vt_c = (lane >> 4) << 3;                           // + dp*16

    for (int pass = 0; pass < 2; pass++) {
        const int qt = pass ? (15 - (int)blockIdx.x) : (int)blockIdx.x;
        const int qbase = qt * 128;
        const int ntiles = 2 * qt + 2;

        // --- load Q (hi+lo) + KV stage 0, one cp.async group ---
        #pragma unroll
        for (int i = 0; i < 8; i++) {
            const int idx = tid + i * 256;         // 0..2047
            const int r = idx >> 4, c = idx & 15;
            const uint32_t so = (uint32_t)(r * AST + c * 8) * 2;
            const size_t go = head_base + (size_t)(qbase + r) * HDIM + c * 8;
            cp16(sb + so, g_Qh + go);
            cp16(sb + Q_BYTES + so, g_Ql + go);
        }
        {
            const uint32_t kvb = sb + 2 * Q_BYTES;
            #pragma unroll
            for (int i = 0; i < 4; i++) {
                const int idx = tid + i * 256;     // 0..1023
                const int r = idx >> 4, c = idx & 15;
                const uint32_t so = (uint32_t)(r * AST + c * 8) * 2;
                const size_t go = head_base + (size_t)r * HDIM + c * 8;
                cp16(kvb + 0 * KV_MAT + so, g_Kh + go);
                cp16(kvb + 1 * KV_MAT + so, g_Kl + go);
                cp16(kvb + 2 * KV_MAT + so, g_Vh + go);
                cp16(kvb + 3 * KV_MAT + so, g_Vl + go);
            }
        }
        CP_COMMIT();

        float o[16][4];
        #pragma unroll
        for (int d = 0; d < 16; d++)
            #pragma unroll
            for (int c = 0; c < 4; c++) o[d][c] = 0.0f;
        float m0 = -1e30f, m1 = -1e30f, l0 = 0.0f, l1 = 0.0f;
        const int wrow = qbase + w * 16;
        const int wqmax = wrow + 15;

        for (int kt = 0; kt < ntiles; kt++) {
            const int st = kt & 1;
            if (kt + 1 < ntiles) {
                const int t1 = (kt + 1) * 64;
                const uint32_t kvb = sb + 2 * Q_BYTES + (uint32_t)(st ^ 1) * KV_STAGE;
                #pragma unroll
                for (int i = 0; i < 4; i++) {
                    const int idx = tid + i * 256;
                    const int r = idx >> 4, c = idx & 15;
                    const uint32_t so = (uint32_t)(r * AST + c * 8) * 2;
                    const size_t go = head_base + (size_t)(t1 + r) * HDIM + c * 8;
                    cp16(kvb + 0 * KV_MAT + so, g_Kh + go);
                    cp16(kvb + 1 * KV_MAT + so, g_Kl + go);
                    cp16(kvb + 2 * KV_MAT + so, g_Vh + go);
                    cp16(kvb + 3 * KV_MAT + so, g_Vl + go);
                }
                CP_COMMIT();
                CP_WAIT(1);
            } else {
                CP_WAIT(0);
            }
            __syncthreads();

            const int t0 = kt * 64;
            if (t0 <= wqmax) {
                const uint32_t kvb = sb + 2 * Q_BYTES + (uint32_t)st * KV_STAGE;

                // ---- scores S = Q @ K^T (bf16x3) ----
                float s[8][4];
                #pragma unroll
                for (int nt = 0; nt < 8; nt++)
                    #pragma unroll
                    for (int c = 0; c < 4; c++) s[nt][c] = 0.0f;

                #pragma unroll
                for (int ks = 0; ks < 8; ks++) {
                    uint32_t qh[4], ql[4];
                    const uint32_t qa = sb + (uint32_t)(qa_r * AST + ks * 16 + qa_c) * 2;
                    LDSM4(qh, qa);
                    LDSM4(ql, qa + Q_BYTES);
                    #pragma unroll
                    for (int np = 0; np < 4; np++) {
                        uint32_t kh[4], kl[4];
                        const uint32_t ka = kvb
                            + (uint32_t)((kb_r + np * 16) * AST + ks * 16 + kb_c) * 2;
                        LDSM4(kh, ka);
                        LDSM4(kl, ka + KV_MAT);
                        MMA16816(s[2 * np],     qh, &kh[0]);
                        MMA16816(s[2 * np],     qh, &kl[0]);
                        MMA16816(s[2 * np],     ql, &kh[0]);
                        MMA16816(s[2 * np + 1], qh, &kh[2]);
                        MMA16816(s[2 * np + 1], qh, &kl[2]);
                        MMA16816(s[2 * np + 1], ql, &kh[2]);
                    }
                }

                // ---- mask (scores already scaled via Q) ----
                if (t0 + 63 > wrow) {
                    const int r0g = wrow + g, r1g = wrow + g + 8;
                    #pragma unroll
                    for (int nt = 0; nt < 8; nt++) {
                        const int cbase = t0 + nt * 8 + tq * 2;
                        if (cbase     > r0g) s[nt][0] = -1e30f;
                        if (cbase + 1 > r0g) s[nt][1] = -1e30f;
                        if (cbase     > r1g) s[nt][2] = -1e30f;
                        if (cbase + 1 > r1g) s[nt][3] = -1e30f;
                    }
                }

                // ---- online softmax ----
                float rm0 = -1e30f, rm1 = -1e30f;
                #pragma unroll
                for (int nt = 0; nt < 8; nt++) {
                    rm0 = fmaxf(rm0, fmaxf(s[nt][0], s[nt][1]));
                    rm1 = fmaxf(rm1, fmaxf(s[nt][2], s[nt][3]));
                }
                rm0 = fmaxf(rm0, __shfl_xor_sync(0xffffffffu, rm0, 1));
                rm0 = fmaxf(rm0, __shfl_xor_sync(0xffffffffu, rm0, 2));
                rm1 = fmaxf(rm1, __shfl_xor_sync(0xffffffffu, rm1, 1));
                rm1 = fmaxf(rm1, __shfl_xor_sync(0xffffffffu, rm1, 2));
                const float mn0 = fmaxf(m0, rm0);
                const float mn1 = fmaxf(m1, rm1);
                const float c0 = __expf(m0 - mn0);
                const float c1 = __expf(m1 - mn1);
                float sum0 = 0.0f, sum1 = 0.0f;
                #pragma unroll
                for (int nt = 0; nt < 8; nt++) {
                    s[nt][0] = __expf(s[nt][0] - mn0);
                    s[nt][1] = __expf(s[nt][1] - mn0);
                    s[nt][2] = __expf(s[nt][2] - mn1);
                    s[nt][3] = __expf(s[nt][3] - mn1);
                    sum0 += s[nt][0] + s[nt][1];
                    sum1 += s[nt][2] + s[nt][3];
                }
                sum0 += __shfl_xor_sync(0xffffffffu, sum0, 1);
                sum0 += __shfl_xor_sync(0xffffffffu, sum0, 2);
                sum1 += __shfl_xor_sync(0xffffffffu, sum1, 1);
                sum1 += __shfl_xor_sync(0xffffffffu, sum1, 2);
                m0 = mn0; m1 = mn1;
                l0 = l0 * c0 + sum0;
                l1 = l1 * c1 + sum1;
                #pragma unroll
                for (int d = 0; d < 16; d++) {
                    o[d][0] *= c0; o[d][1] *= c0;
                    o[d][2] *= c1; o[d][3] *= c1;
                }

                // ---- P fragments (hi/lo) ----
                uint32_t ph[4][4], pl[4][4];
                #pragma unroll
                for (int k2 = 0; k2 < 4; k2++) {
                    ph[k2][0] = bf2pack(s[2 * k2][0],     s[2 * k2][1]);
                    ph[k2][1] = bf2pack(s[2 * k2][2],     s[2 * k2][3]);
                    ph[k2][2] = bf2pack(s[2 * k2 + 1][0], s[2 * k2 + 1][1]);
                    ph[k2][3] = bf2pack(s[2 * k2 + 1][2], s[2 * k2 + 1][3]);
                    pl[k2][0] = bf2pack(bf16res(s[2 * k2][0]),     bf16res(s[2 * k2][1]));
                    pl[k2][1] = bf2pack(bf16res(s[2 * k2][2]),     bf16res(s[2 * k2][3]));
                    pl[k2][2] = bf2pack(bf16res(s[2 * k2 + 1][0]), bf16res(s[2 * k2 + 1][1]));
                    pl[k2][3] = bf2pack(bf16res(s[2 * k2 + 1][2]), bf16res(s[2 * k2 + 1][3]));
                }

                // ---- O += P @ V (bf16x3, V via ldmatrix.trans) ----
                #pragma unroll
                for (int k2 = 0; k2 < 4; k2++) {
                    #pragma unroll
                    for (int dp = 0; dp < 8; dp++) {
                        uint32_t vh[4], vl[4];
                        const uint32_t va = kvb + 2 * KV_MAT
                            + (uint32_t)((k2 * 16 + vt_r) * AST + dp * 16 + vt_c) * 2;
                        LDSM4T(vh, va);
                        LDSM4T(vl, va + KV_MAT);
                        MMA16816(o[2 * dp],     ph[k2], &vh[0]);
                        MMA16816(o[2 * dp],     ph[k2], &vl[0]);
                        MMA16816(o[2 * dp],     pl[k2], &vh[0]);
                        MMA16816(o[2 * dp + 1], ph[k2], &vh[2]);
                        MMA16816(o[2 * dp + 1], ph[k2], &vl[2]);
                        MMA16816(o[2 * dp + 1], pl[k2], &vh[2]);
                    }
                }
            }
            __syncthreads();
        }

        // ---- normalize + write ctx ----
        const float inv0 = 1.0f / l0;
        const float inv1 = 1.0f / l1;
        const int r0g = qbase + w * 16 + g;
        const int r1g = r0g + 8;
        float* base0 = ctx + ((size_t)r0g * BATCH + b) * HIDDEN + h * HDIM + tq * 2;
        float* base1 = ctx + ((size_t)r1g * BATCH + b) * HIDDEN + h * HDIM + tq * 2;
        #pragma unroll
        for (int d = 0; d < 16; d++) {
            *(float2*)(base0 + d * 8) = make_float2(o[d][0] * inv0, o[d][1] * inv0);
            *(float2*)(base1 + d * 8) = make_float2(o[d][2] * inv1, o[d][3] * inv1);
        }
        __syncthreads();
    }
}

__global__ void copy_bias_kernel(const float* __restrict__ b, float* __restrict__ o)
{
    const int i = blockIdx.x * blockDim.x + threadIdx.x;
    if (i < HIDDEN) o[i] = b[i];
}

// ---------------------------------------------------------------------------
// Launch
// ---------------------------------------------------------------------------
extern "C" void kernel_launch(void* const* d_in, const int* in_sizes, int n_in,
                              void* d_out, int out_size)
{
    const float* hidden  = (const float*)d_in[0];
    const float* w_qkv   = (const float*)d_in[2];
    const float* b_qkv   = (const float*)d_in[3];
    const float* w_dense = (const float*)d_in[4];
    const float* b_dense = (const float*)d_in[5];
    float* out = (float*)d_out;

    float *qkv = nullptr, *ctx = nullptr;
    __nv_bfloat16 *Ahi, *Alo, *Bqh, *Bql, *Bdh, *Bdl;
    cudaGetSymbolAddress((void**)&qkv, g_qkv);
    cudaGetSymbolAddress((void**)&ctx, g_ctx);
    cudaGetSymbolAddress((void**)&Ahi, g_Ahi);
    cudaGetSymbolAddress((void**)&Alo, g_Alo);
    cudaGetSymbolAddress((void**)&Bqh, g_Bqkv_hi);
    cudaGetSymbolAddress((void**)&Bql, g_Bqkv_lo);
    cudaGetSymbolAddress((void**)&Bdh, g_Bd_hi);
    cudaGetSymbolAddress((void**)&Bdl, g_Bd_lo);

    cudaFuncSetAttribute(gemm_bf16x3_mma_kernel,
                         cudaFuncAttributeMaxDynamicSharedMemorySize, GEMM_SMEM);
    cudaFuncSetAttribute(attn_mma_kernel,
                         cudaFuncAttributeMaxDynamicSharedMemorySize, ATTN_SMEM);

    const int n4_act = (M_ROWS * HIDDEN) / 4;

    // 1. Split inputs + weights for QKV
    split_rm_kernel<<<(n4_act + 255) / 256, 256>>>(hidden, Ahi, Alo, n4_act);
    split_tr_kernel<<<dim3(QKV_N / 32, HIDDEN / 32), dim3(32, 8)>>>(
        w_qkv, Bqh, Bql, HIDDEN, QKV_N);

    // 2. QKV projection
    gemm_bf16x3_mma_kernel<<<dim3(QKV_N / 128, M_ROWS / 128), 256, GEMM_SMEM>>>(
        Ahi, Alo, Bqh, Bql, b_qkv, qkv, M_ROWS, QKV_N, HIDDEN);

    // 3. Split qkv into per-head Q(scaled)/K/V bf16 hi/lo
    qkv_split_kernel<<<(32 * SEQ * 32) / 256, 256>>>(qkv);

    // 4. Causal flash attention (mma.sync bf16x3)
    attn_mma_kernel<<<dim3(8, 32), 256, ATTN_SMEM>>>(ctx);

    // 5. Dense projection (skip_bias_add)
    split_rm_kernel<<<(n4_act + 255) / 256, 256>>>(ctx, Ahi, Alo, n4_act);
    split_tr_kernel<<<dim3(HIDDEN / 32, HIDDEN / 32), dim3(32, 8)>>>(
        w_dense, Bdh, Bdl, HIDDEN, HIDDEN);
    gemm_bf16x3_mma_kernel<<<dim3(HIDDEN / 128, M_ROWS / 128), 256, GEMM_SMEM>>>(
        Ahi, Alo, Bdh, Bdl, nullptr, out, M_ROWS, HIDDEN, HIDDEN);

    // 6. b_dense returned separately -> output tail (if present)
    if (out_size >= M_ROWS * HIDDEN + HIDDEN) {
        copy_bias_kernel<<<(HIDDEN + 255) / 256, 256>>>(
            b_dense, out + (size_t)M_ROWS * HIDDEN);
    }
}

// round 8
// speedup vs baseline: 3.2122x; 1.1931x over previous
#include <cuda_runtime.h>
#include <cuda_bf16.h>
#include <cstdint>

// Problem constants
#define SEQ     2048
#define BATCH   2
#define HIDDEN  2048
#define NHEADS  16
#define HDIM    128
#define M_ROWS  (SEQ * BATCH)       // 4096
#define QKV_N   (3 * HIDDEN)        // 6144

// ---------------------------------------------------------------------------
// Scratch (device globals: allocation-free per harness rules)
// ---------------------------------------------------------------------------
__device__ __nv_bfloat16 g_Ahi[(size_t)M_ROWS * HIDDEN];
__device__ __nv_bfloat16 g_Alo[(size_t)M_ROWS * HIDDEN];
__device__ __nv_bfloat16 g_Bqkv_hi[(size_t)QKV_N * HIDDEN];
__device__ __nv_bfloat16 g_Bqkv_lo[(size_t)QKV_N * HIDDEN];
__device__ __nv_bfloat16 g_Bd_hi[(size_t)HIDDEN * HIDDEN];
__device__ __nv_bfloat16 g_Bd_lo[(size_t)HIDDEN * HIDDEN];
// attention per-head split arrays [bh][s][d], bh = b*16+h
#define HSZ ((size_t)32 * SEQ * HDIM)
__device__ __nv_bfloat16 g_Qh[HSZ];
__device__ __nv_bfloat16 g_Ql[HSZ];
__device__ __nv_bfloat16 g_Kh[HSZ];
__device__ __nv_bfloat16 g_Kl[HSZ];
__device__ __nv_bfloat16 g_Vh[HSZ];
__device__ __nv_bfloat16 g_Vl[HSZ];

// ---------------------------------------------------------------------------
// Helpers
// ---------------------------------------------------------------------------
__device__ __forceinline__ uint32_t smem_to_u32(const void* p) {
    uint32_t a;
    asm("{ .reg .u64 t; cvta.to.shared.u64 t, %1; cvt.u32.u64 %0, t; }" : "=r"(a) : "l"(p));
    return a;
}
__device__ __forceinline__ void cp16(uint32_t s, const void* g) {
    asm volatile("cp.async.cg.shared.global [%0], [%1], 16;" :: "r"(s), "l"(g));
}
#define CP_COMMIT() asm volatile("cp.async.commit_group;" ::: "memory")
#define CP_WAIT(n)  asm volatile("cp.async.wait_group %0;" :: "n"(n) : "memory")

#define MMA16816(d, a, b) \
    asm volatile("mma.sync.aligned.m16n8k16.row.col.f32.bf16.bf16.f32 " \
        "{%0,%1,%2,%3}, {%4,%5,%6,%7}, {%8,%9}, {%0,%1,%2,%3};" \
        : "+f"((d)[0]), "+f"((d)[1]), "+f"((d)[2]), "+f"((d)[3]) \
        : "r"((a)[0]), "r"((a)[1]), "r"((a)[2]), "r"((a)[3]), \
          "r"((b)[0]), "r"((b)[1]))

#define LDSM4(r, addr) \
    asm volatile("ldmatrix.sync.aligned.m8n8.x4.shared.b16 {%0,%1,%2,%3}, [%4];" \
        : "=r"((r)[0]), "=r"((r)[1]), "=r"((r)[2]), "=r"((r)[3]) : "r"(addr))
#define LDSM4T(r, addr) \
    asm volatile("ldmatrix.sync.aligned.m8n8.x4.trans.shared.b16 {%0,%1,%2,%3}, [%4];" \
        : "=r"((r)[0]), "=r"((r)[1]), "=r"((r)[2]), "=r"((r)[3]) : "r"(addr))

__device__ __forceinline__ uint32_t bf2pack(float a, float b) {
    __nv_bfloat162 t = __floats2bfloat162_rn(a, b);
    return *(uint32_t*)&t;
}
__device__ __forceinline__ float bf16res(float x) {
    return x - __bfloat162float(__float2bfloat16(x));
}
__device__ __forceinline__ __nv_bfloat162 split_hi2(float a, float b) {
    return __nv_bfloat162(__float2bfloat16(a), __float2bfloat16(b));
}
__device__ __forceinline__ __nv_bfloat162 split_lo2(float a, float b) {
    return __nv_bfloat162(__float2bfloat16(bf16res(a)), __float2bfloat16(bf16res(b)));
}

// ---------------------------------------------------------------------------
// Conversion kernels
// ---------------------------------------------------------------------------
__global__ void split_rm_kernel(const float* __restrict__ in,
                                __nv_bfloat16* __restrict__ hi,
                                __nv_bfloat16* __restrict__ lo, int n4)
{
    int i = blockIdx.x * blockDim.x + threadIdx.x;
    if (i >= n4) return;
    float4 v = ((const float4*)in)[i];
    ((__nv_bfloat162*)hi)[2 * i]     = split_hi2(v.x, v.y);
    ((__nv_bfloat162*)hi)[2 * i + 1] = split_hi2(v.z, v.w);
    ((__nv_bfloat162*)lo)[2 * i]     = split_lo2(v.x, v.y);
    ((__nv_bfloat162*)lo)[2 * i + 1] = split_lo2(v.z, v.w);
}

__global__ void split_tr_kernel(const float* __restrict__ in,
                                __nv_bfloat16* __restrict__ hi,
                                __nv_bfloat16* __restrict__ lo, int K, int N)
{
    __shared__ float t[32][33];
    const int n0 = blockIdx.x * 32, k0 = blockIdx.y * 32;
    const int tx = threadIdx.x, ty = threadIdx.y;
    #pragma unroll
    for (int i = 0; i < 4; i++)
        t[ty + 8 * i][tx] = in[(size_t)(k0 + ty + 8 * i) * N + n0 + tx];
    __syncthreads();
    #pragma unroll
    for (int i = 0; i < 4; i++) {
        const int r = ty + 8 * i;
        const float x = t[tx][r];
        __nv_bfloat16 h = __float2bfloat16(x);
        __nv_bfloat16 l = __float2bfloat16(x - __bfloat162float(h));
        const size_t o = (size_t)(n0 + r) * K + k0 + tx;
        hi[o] = h; lo[o] = l;
    }
}

// ---------------------------------------------------------------------------
// bf16x3 mma.sync GEMM with ldmatrix + fused epilogues.
// C[M,N] = A[M,K] @ B^T (B stored [N,K]); D = AhBh + AhBl + AlBh.
// CTA 128x128, BK=32, 8 warps, cp.async double buffer, 2 CTAs/SM.
// out_mode 0: fp32 C (+bias optional). out_mode 1: QKV split epilogue
//   (bias + Q-scale, write per-head bf16 hi/lo arrays directly).
// ---------------------------------------------------------------------------
#define GBK 32
#define LDS_STRIDE 40
#define MAT_BYTES (128 * LDS_STRIDE * 2)
#define STAGE_BYTES (4 * MAT_BYTES)
#define GEMM_SMEM (2 * STAGE_BYTES)      // 81920 -> 2 CTAs/SM

__global__ __launch_bounds__(256, 2) void gemm_bf16x3_mma_kernel(
    const __nv_bfloat16* __restrict__ Ahi, const __nv_bfloat16* __restrict__ Alo,
    const __nv_bfloat16* __restrict__ Bhi, const __nv_bfloat16* __restrict__ Blo,
    const float* __restrict__ bias, float* __restrict__ C,
    int M, int N, int K, int out_mode)
{
    extern __shared__ char smem[];
    const uint32_t sbase = smem_to_u32(smem);
    const int tid  = threadIdx.x;
    const int wid  = tid >> 5;
    const int lane = tid & 31;
    const int g    = lane >> 2;
    const int tq   = lane & 3;
    const int wm   = wid & 3;
    const int wn   = wid >> 2;
    const int row0 = blockIdx.y * 128;
    const int col0 = blockIdx.x * 128;
    const int NC   = K / GBK;

    const int l_row = tid >> 2;
    const int l_kc  = (tid & 3) * 8;

    float acc[2][8][4];
    #pragma unroll
    for (int mt = 0; mt < 2; mt++)
        #pragma unroll
        for (int nt = 0; nt < 8; nt++)
            #pragma unroll
            for (int q = 0; q < 4; q++) acc[mt][nt][q] = 0.0f;

    auto load_stage = [&](int st, int kc) {
        const int kel = kc * GBK;
        const uint32_t stb = sbase + (uint32_t)st * STAGE_BYTES;
        #pragma unroll
        for (int i = 0; i < 2; i++) {
            const int row = l_row + i * 64;
            const uint32_t soff = (uint32_t)(row * LDS_STRIDE + l_kc) * 2;
            const size_t ga = (size_t)(row0 + row) * K + kel + l_kc;
            const size_t gb = (size_t)(col0 + row) * K + kel + l_kc;
            cp16(stb + 0 * MAT_BYTES + soff, Ahi + ga);
            cp16(stb + 1 * MAT_BYTES + soff, Alo + ga);
            cp16(stb + 2 * MAT_BYTES + soff, Bhi + gb);
            cp16(stb + 3 * MAT_BYTES + soff, Blo + gb);
        }
        CP_COMMIT();
    };

    load_stage(0, 0);

    const int a_r = wm * 32 + (lane & 15);
    const int a_c = (lane >> 4) << 3;
    const int b_r = wn * 64 + (lane & 7) + (((lane >> 4) & 1) << 3);
    const int b_c = ((lane >> 3) & 1) << 3;

    for (int kc = 0; kc < NC; kc++) {
        const int st = kc & 1;
        if (kc + 1 < NC) { load_stage(st ^ 1, kc + 1); CP_WAIT(1); }
        else             { CP_WAIT(0); }
        __syncthreads();

        const uint32_t stb = sbase + (uint32_t)st * STAGE_BYTES;

        #pragma unroll
        for (int ks = 0; ks < GBK; ks += 16) {
            uint32_t ah[2][4], al[2][4];
            #pragma unroll
            for (int mt = 0; mt < 2; mt++) {
                const uint32_t aa = stb + (uint32_t)(((a_r + mt * 16) * LDS_STRIDE) + ks + a_c) * 2;
                LDSM4(ah[mt], aa);
                LDSM4(al[mt], aa + MAT_BYTES);
            }
            uint32_t bh[4][4], bl[4][4];
            #pragma unroll
            for (int np = 0; np < 4; np++) {
                const uint32_t ba = stb + 2 * MAT_BYTES
                    + (uint32_t)(((b_r + np * 16) * LDS_STRIDE) + ks + b_c) * 2;
                LDSM4(bh[np], ba);
                LDSM4(bl[np], ba + MAT_BYTES);
            }
            #pragma unroll
            for (int mt = 0; mt < 2; mt++)
                #pragma unroll
                for (int nt = 0; nt < 8; nt++) {
                    uint32_t* bhp = &bh[nt >> 1][(nt & 1) * 2];
                    uint32_t* blp = &bl[nt >> 1][(nt & 1) * 2];
                    MMA16816(acc[mt][nt], ah[mt], bhp);
                    MMA16816(acc[mt][nt], ah[mt], blp);
                    MMA16816(acc[mt][nt], al[mt], bhp);
                }
        }
        __syncthreads();
    }

    if (out_mode == 0) {
        #pragma unroll
        for (int mt = 0; mt < 2; mt++) {
            const int r1 = row0 + wm * 32 + mt * 16 + g;
            const int r2 = r1 + 8;
            #pragma unroll
            for (int nt = 0; nt < 8; nt++) {
                const int c = col0 + wn * 64 + nt * 8 + tq * 2;
                float2 o1 = make_float2(acc[mt][nt][0], acc[mt][nt][1]);
                float2 o2 = make_float2(acc[mt][nt][2], acc[mt][nt][3]);
                if (bias) {
                    const float b0 = bias[c], b1 = bias[c + 1];
                    o1.x += b0; o1.y += b1;
                    o2.x += b0; o2.y += b1;
                }
                *(float2*)(C + (size_t)r1 * N + c) = o1;
                *(float2*)(C + (size_t)r2 * N + c) = o2;
            }
        }
    } else {
        // QKV fused epilogue: bias add, Q pre-scale, bf16 hi/lo split,
        // write per-head arrays [bh][s][d].
        const float qs = 0.08838834764831845f;
        #pragma unroll
        for (int mt = 0; mt < 2; mt++) {
            const int r1 = row0 + wm * 32 + mt * 16 + g;
            const int r2 = r1 + 8;
            const int s1 = r1 >> 1, b1 = r1 & 1;
            const int s2 = r2 >> 1, b2 = r2 & 1;
            #pragma unroll
            for (int nt = 0; nt < 8; nt++) {
                const int c = col0 + wn * 64 + nt * 8 + tq * 2;
                const int h = c / 384;
                const int rem = c - h * 384;
                const int m = rem >> 7;
                const int d = rem & 127;
                float v10 = acc[mt][nt][0] + bias[c];
                float v11 = acc[mt][nt][1] + bias[c + 1];
                float v20 = acc[mt][nt][2] + bias[c];
                float v21 = acc[mt][nt][3] + bias[c + 1];
                if (m == 0) { v10 *= qs; v11 *= qs; v20 *= qs; v21 *= qs; }
                __nv_bfloat16* hi = (m == 0) ? g_Qh : (m == 1) ? g_Kh : g_Vh;
                __nv_bfloat16* lo = (m == 0) ? g_Ql : (m == 1) ? g_Kl : g_Vl;
                const size_t o1 = ((size_t)(b1 * 16 + h) * SEQ + s1) * HDIM + d;
                const size_t o2 = ((size_t)(b2 * 16 + h) * SEQ + s2) * HDIM + d;
                *(__nv_bfloat162*)(hi + o1) = split_hi2(v10, v11);
                *(__nv_bfloat162*)(lo + o1) = split_lo2(v10, v11);
                *(__nv_bfloat162*)(hi + o2) = split_hi2(v20, v21);
                *(__nv_bfloat162*)(lo + o2) = split_lo2(v20, v21);
            }
        }
    }
}

// ---------------------------------------------------------------------------
// Flash attention, bf16x3 mma.sync, causal. Output written pre-split
// (bf16 hi/lo) directly into g_Ahi/g_Alo in ctx layout for the dense GEMM.
// ---------------------------------------------------------------------------
#define AST 136
#define Q_BYTES (128 * AST * 2)
#define KV_MAT (64 * AST * 2)
#define KV_STAGE (4 * KV_MAT)
#define ATTN_SMEM (2 * Q_BYTES + 2 * KV_STAGE)

__global__ __launch_bounds__(256) void attn_mma_kernel()
{
    extern __shared__ char smem[];
    const uint32_t sb = smem_to_u32(smem);
    const int tid  = threadIdx.x;
    const int lane = tid & 31;
    const int w    = tid >> 5;
    const int g    = lane >> 2;
    const int tq   = lane & 3;
    const int bh   = blockIdx.y;
    const int b    = bh >> 4;
    const int h    = bh & 15;
    const size_t head_base = (size_t)bh * SEQ * HDIM;

    const int qa_r = w * 16 + (lane & 15);
    const int qa_c = (lane >> 4) << 3;
    const int kb_r = (lane & 7) + (((lane >> 4) & 1) << 3);
    const int kb_c = ((lane >> 3) & 1) << 3;
    const int vt_r = lane & 15;
    const int vt_c = (lane >> 4) << 3;

    for (int pass = 0; pass < 2; pass++) {
        const int qt = pass ? (15 - (int)blockIdx.x) : (int)blockIdx.x;
        const int qbase = qt * 128;
        const int ntiles = 2 * qt + 2;

        #pragma unroll
        for (int i = 0; i < 8; i++) {
            const int idx = tid + i * 256;
            const int r = idx >> 4, c = idx & 15;
            const uint32_t so = (uint32_t)(r * AST + c * 8) * 2;
            const size_t go = head_base + (size_t)(qbase + r) * HDIM + c * 8;
            cp16(sb + so, g_Qh + go);
            cp16(sb + Q_BYTES + so, g_Ql + go);
        }
        {
            const uint32_t kvb = sb + 2 * Q_BYTES;
            #pragma unroll
            for (int i = 0; i < 4; i++) {
                const int idx = tid + i * 256;
                const int r = idx >> 4, c = idx & 15;
                const uint32_t so = (uint32_t)(r * AST + c * 8) * 2;
                const size_t go = head_base + (size_t)r * HDIM + c * 8;
                cp16(kvb + 0 * KV_MAT + so, g_Kh + go);
                cp16(kvb + 1 * KV_MAT + so, g_Kl + go);
                cp16(kvb + 2 * KV_MAT + so, g_Vh + go);
                cp16(kvb + 3 * KV_MAT + so, g_Vl + go);
            }
        }
        CP_COMMIT();

        float o[16][4];
        #pragma unroll
        for (int d = 0; d < 16; d++)
            #pragma unroll
            for (int c = 0; c < 4; c++) o[d][c] = 0.0f;
        float m0 = -1e30f, m1 = -1e30f, l0 = 0.0f, l1 = 0.0f;
        const int wrow = qbase + w * 16;
        const int wqmax = wrow + 15;

        for (int kt = 0; kt < ntiles; kt++) {
            const int st = kt & 1;
            if (kt + 1 < ntiles) {
                const int t1 = (kt + 1) * 64;
                const uint32_t kvb = sb + 2 * Q_BYTES + (uint32_t)(st ^ 1) * KV_STAGE;
                #pragma unroll
                for (int i = 0; i < 4; i++) {
                    const int idx = tid + i * 256;
                    const int r = idx >> 4, c = idx & 15;
                    const uint32_t so = (uint32_t)(r * AST + c * 8) * 2;
                    const size_t go = head_base + (size_t)(t1 + r) * HDIM + c * 8;
                    cp16(kvb + 0 * KV_MAT + so, g_Kh + go);
                    cp16(kvb + 1 * KV_MAT + so, g_Kl + go);
                    cp16(kvb + 2 * KV_MAT + so, g_Vh + go);
                    cp16(kvb + 3 * KV_MAT + so, g_Vl + go);
                }
                CP_COMMIT();
                CP_WAIT(1);
            } else {
                CP_WAIT(0);
            }
            __syncthreads();

            const int t0 = kt * 64;
            if (t0 <= wqmax) {
                const uint32_t kvb = sb + 2 * Q_BYTES + (uint32_t)st * KV_STAGE;

                float s[8][4];
                #pragma unroll
                for (int nt = 0; nt < 8; nt++)
                    #pragma unroll
                    for (int c = 0; c < 4; c++) s[nt][c] = 0.0f;

                #pragma unroll
                for (int ks = 0; ks < 8; ks++) {
                    uint32_t qh[4], ql[4];
                    const uint32_t qa = sb + (uint32_t)(qa_r * AST + ks * 16 + qa_c) * 2;
                    LDSM4(qh, qa);
                    LDSM4(ql, qa + Q_BYTES);
                    #pragma unroll
                    for (int np = 0; np < 4; np++) {
                        uint32_t kh[4], kl[4];
                        const uint32_t ka = kvb
                            + (uint32_t)((kb_r + np * 16) * AST + ks * 16 + kb_c) * 2;
                        LDSM4(kh, ka);
                        LDSM4(kl, ka + KV_MAT);
                        MMA16816(s[2 * np],     qh, &kh[0]);
                        MMA16816(s[2 * np],     qh, &kl[0]);
                        MMA16816(s[2 * np],     ql, &kh[0]);
                        MMA16816(s[2 * np + 1], qh, &kh[2]);
                        MMA16816(s[2 * np + 1], qh, &kl[2]);
                        MMA16816(s[2 * np + 1], ql, &kh[2]);
                    }
                }

                if (t0 + 63 > wrow) {
                    const int r0g = wrow + g, r1g = wrow + g + 8;
                    #pragma unroll
                    for (int nt = 0; nt < 8; nt++) {
                        const int cbase = t0 + nt * 8 + tq * 2;
                        if (cbase     > r0g) s[nt][0] = -1e30f;
                        if (cbase + 1 > r0g) s[nt][1] = -1e30f;
                        if (cbase     > r1g) s[nt][2] = -1e30f;
                        if (cbase + 1 > r1g) s[nt][3] = -1e30f;
                    }
                }

                float rm0 = -1e30f, rm1 = -1e30f;
                #pragma unroll
                for (int nt = 0; nt < 8; nt++) {
                    rm0 = fmaxf(rm0, fmaxf(s[nt][0], s[nt][1]));
                    rm1 = fmaxf(rm1, fmaxf(s[nt][2], s[nt][3]));
                }
                rm0 = fmaxf(rm0, __shfl_xor_sync(0xffffffffu, rm0, 1));
                rm0 = fmaxf(rm0, __shfl_xor_sync(0xffffffffu, rm0, 2));
                rm1 = fmaxf(rm1, __shfl_xor_sync(0xffffffffu, rm1, 1));
                rm1 = fmaxf(rm1, __shfl_xor_sync(0xffffffffu, rm1, 2));
                const float mn0 = fmaxf(m0, rm0);
                const float mn1 = fmaxf(m1, rm1);
                const float c0 = __expf(m0 - mn0);
                const float c1 = __expf(m1 - mn1);
                float sum0 = 0.0f, sum1 = 0.0f;
                #pragma unroll
                for (int nt = 0; nt < 8; nt++) {
                    s[nt][0] = __expf(s[nt][0] - mn0);
                    s[nt][1] = __expf(s[nt][1] - mn0);
                    s[nt][2] = __expf(s[nt][2] - mn1);
                    s[nt][3] = __expf(s[nt][3] - mn1);
                    sum0 += s[nt][0] + s[nt][1];
                    sum1 += s[nt][2] + s[nt][3];
                }
                sum0 += __shfl_xor_sync(0xffffffffu, sum0, 1);
                sum0 += __shfl_xor_sync(0xffffffffu, sum0, 2);
                sum1 += __shfl_xor_sync(0xffffffffu, sum1, 1);
                sum1 += __shfl_xor_sync(0xffffffffu, sum1, 2);
                m0 = mn0; m1 = mn1;
                l0 = l0 * c0 + sum0;
                l1 = l1 * c1 + sum1;
                #pragma unroll
                for (int d = 0; d < 16; d++) {
                    o[d][0] *= c0; o[d][1] *= c0;
                    o[d][2] *= c1; o[d][3] *= c1;
                }

                uint32_t ph[4][4], pl[4][4];
                #pragma unroll
                for (int k2 = 0; k2 < 4; k2++) {
                    ph[k2][0] = bf2pack(s[2 * k2][0],     s[2 * k2][1]);
                    ph[k2][1] = bf2pack(s[2 * k2][2],     s[2 * k2][3]);
                    ph[k2][2] = bf2pack(s[2 * k2 + 1][0], s[2 * k2 + 1][1]);
                    ph[k2][3] = bf2pack(s[2 * k2 + 1][2], s[2 * k2 + 1][3]);
                    pl[k2][0] = bf2pack(bf16res(s[2 * k2][0]),     bf16res(s[2 * k2][1]));
                    pl[k2][1] = bf2pack(bf16res(s[2 * k2][2]),     bf16res(s[2 * k2][3]));
                    pl[k2][2] = bf2pack(bf16res(s[2 * k2 + 1][0]), bf16res(s[2 * k2 + 1][1]));
                    pl[k2][3] = bf2pack(bf16res(s[2 * k2 + 1][2]), bf16res(s[2 * k2 + 1][3]));
                }

                #pragma unroll
                for (int k2 = 0; k2 < 4; k2++) {
                    #pragma unroll
                    for (int dp = 0; dp < 8; dp++) {
                        uint32_t vh[4], vl[4];
                        const uint32_t va = kvb + 2 * KV_MAT
                            + (uint32_t)((k2 * 16 + vt_r) * AST + dp * 16 + vt_c) * 2;
                        LDSM4T(vh, va);
                        LDSM4T(vl, va + KV_MAT);
                        MMA16816(o[2 * dp],     ph[k2], &vh[0]);
                        MMA16816(o[2 * dp],     ph[k2], &vl[0]);
                        MMA16816(o[2 * dp],     pl[k2], &vh[0]);
                        MMA16816(o[2 * dp + 1], ph[k2], &vh[2]);
                        MMA16816(o[2 * dp + 1], ph[k2], &vl[2]);
                        MMA16816(o[2 * dp + 1], pl[k2], &vh[2]);
                    }
                }
            }
            __syncthreads();
        }

        // normalize + write ctx pre-split (bf16 hi/lo) for the dense GEMM
        const float inv0 = 1.0f / l0;
        const float inv1 = 1.0f / l1;
        const int r0g = qbase + w * 16 + g;
        const int r1g = r0g + 8;
        const size_t off0 = ((size_t)r0g * BATCH + b) * HIDDEN + h * HDIM + tq * 2;
        const size_t off1 = ((size_t)r1g * BATCH + b) * HIDDEN + h * HDIM + tq * 2;
        #pragma unroll
        for (int d = 0; d < 16; d++) {
            const float a0 = o[d][0] * inv0, a1 = o[d][1] * inv0;
            const float a2 = o[d][2] * inv1, a3 = o[d][3] * inv1;
            *(__nv_bfloat162*)(g_Ahi + off0 + d * 8) = split_hi2(a0, a1);
            *(__nv_bfloat162*)(g_Alo + off0 + d * 8) = split_lo2(a0, a1);
            *(__nv_bfloat162*)(g_Ahi + off1 + d * 8) = split_hi2(a2, a3);
            *(__nv_bfloat162*)(g_Alo + off1 + d * 8) = split_lo2(a2, a3);
        }
        __syncthreads();
    }
}

__global__ void copy_bias_kernel(const float* __restrict__ b, float* __restrict__ o)
{
    const int i = blockIdx.x * blockDim.x + threadIdx.x;
    if (i < HIDDEN) o[i] = b[i];
}

// ---------------------------------------------------------------------------
// Launch
// ---------------------------------------------------------------------------
extern "C" void kernel_launch(void* const* d_in, const int* in_sizes, int n_in,
                              void* d_out, int out_size)
{
    const float* hidden  = (const float*)d_in[0];
    const float* w_qkv   = (const float*)d_in[2];
    const float* b_qkv   = (const float*)d_in[3];
    const float* w_dense = (const float*)d_in[4];
    const float* b_dense = (const float*)d_in[5];
    float* out = (float*)d_out;

    __nv_bfloat16 *Ahi, *Alo, *Bqh, *Bql, *Bdh, *Bdl;
    cudaGetSymbolAddress((void**)&Ahi, g_Ahi);
    cudaGetSymbolAddress((void**)&Alo, g_Alo);
    cudaGetSymbolAddress((void**)&Bqh, g_Bqkv_hi);
    cudaGetSymbolAddress((void**)&Bql, g_Bqkv_lo);
    cudaGetSymbolAddress((void**)&Bdh, g_Bd_hi);
    cudaGetSymbolAddress((void**)&Bdl, g_Bd_lo);

    cudaFuncSetAttribute(gemm_bf16x3_mma_kernel,
                         cudaFuncAttributeMaxDynamicSharedMemorySize, GEMM_SMEM);
    cudaFuncSetAttribute(attn_mma_kernel,
                         cudaFuncAttributeMaxDynamicSharedMemorySize, ATTN_SMEM);

    const int n4_act = (M_ROWS * HIDDEN) / 4;

    // 1. Split hidden + w_qkv
    split_rm_kernel<<<(n4_act + 255) / 256, 256>>>(hidden, Ahi, Alo, n4_act);
    split_tr_kernel<<<dim3(QKV_N / 32, HIDDEN / 32), dim3(32, 8)>>>(
        w_qkv, Bqh, Bql, HIDDEN, QKV_N);

    // 2. QKV projection with fused per-head split epilogue (mode 1)
    gemm_bf16x3_mma_kernel<<<dim3(QKV_N / 128, M_ROWS / 128), 256, GEMM_SMEM>>>(
        Ahi, Alo, Bqh, Bql, b_qkv, nullptr, M_ROWS, QKV_N, HIDDEN, 1);

    // 3. Causal flash attention (writes ctx pre-split into Ahi/Alo)
    attn_mma_kernel<<<dim3(8, 32), 256, ATTN_SMEM>>>();

    // 4. Dense projection (skip_bias_add), fp32 out (mode 0)
    split_tr_kernel<<<dim3(HIDDEN / 32, HIDDEN / 32), dim3(32, 8)>>>(
        w_dense, Bdh, Bdl, HIDDEN, HIDDEN);
    gemm_bf16x3_mma_kernel<<<dim3(HIDDEN / 128, M_ROWS / 128), 256, GEMM_SMEM>>>(
        Ahi, Alo, Bdh, Bdl, nullptr, out, M_ROWS, HIDDEN, HIDDEN, 0);

    // 5. b_dense returned separately -> output tail (if present)
    if (out_size >= M_ROWS * HIDDEN + HIDDEN) {
        copy_bias_kernel<<<(HIDDEN + 255) / 256, 256>>>(
            b_dense, out + (size_t)M_ROWS * HIDDEN);
    }
}